// round 14
// baseline (speedup 1.0000x reference)
#include <cuda_runtime.h>
#include <cuda_fp16.h>
#include <math.h>
#include <stdint.h>

#define D    1024
#define DFF  4096
#define E    8
#define TOK  8192
#define BM   128
#define BN   256
#define NT   512
#define NSM  148
#define A2   32768           // A stage bytes (2 x 16KB kc chunks)
#define B2   65536           // B stage bytes (2 x 32KB kc chunks)
#define STGB (A2+B2)         // 98304
#define SMEM_BYTES (1024 + 2*STGB)   // 197632
#define MAXROWS (2*TOK + E*BM)     // 17408
#define NROWT (MAXROWS/BM)         // 136

// ---------------- scratch ----------------
__device__ int   g_eid[TOK*2];
__device__ float g_gw[TOK*2];
__device__ int   g_counts[E];
__device__ int   g_off[E+1];
__device__ int   g_cursor[E];
__device__ int   g_total;
__device__ int   g_slot_token[MAXROWS];
__device__ int   g_slot_of[TOK*2];
__device__ float g_usage[E];
__device__ uint8_t g_xa[(size_t)NROWT*16*16384];       // [tile][kc][16KB]
__device__ uint8_t g_w1t[(size_t)E*16*16*32768];       // [e][nb][kc][32KB]
__device__ uint8_t g_w2t[(size_t)E*4*64*32768];        // [e][nb][kc][32KB]
__device__ uint8_t g_ht[(size_t)NROWT*64*16384];       // [tile][kc][16KB]
__device__ float   g_y[(size_t)MAXROWS*D];

// ---------------- helpers ----------------
__device__ __forceinline__ uint32_t smem_u32(const void* p) {
    uint32_t a;
    asm("{ .reg .u64 t; cvta.to.shared.u64 t, %1; cvt.u32.u64 %0, t; }" : "=r"(a) : "l"(p));
    return a;
}
#define MBAR_INIT(a,c) asm volatile("mbarrier.init.shared.b64 [%0], %1;" :: "r"(a), "r"(c) : "memory")
#define MBAR_EXPECT(a,tx) asm volatile("mbarrier.arrive.expect_tx.shared.b64 _, [%0], %1;" :: "r"(a), "r"(tx) : "memory")
#define BULK(dst, src, sz, bar) asm volatile( \
    "cp.async.bulk.shared::cluster.global.mbarrier::complete_tx::bytes [%0], [%1], %2, [%3];" \
    :: "r"(dst), "l"(src), "r"(sz), "r"(bar) : "memory")
#define MBAR_WAIT(a,p) do { uint32_t _m=(a); uint32_t _p=(p); uint32_t _d; \
    asm volatile("{\n\t.reg .pred p;\n\tmbarrier.try_wait.parity.acquire.cta.shared::cta.b64 p, [%1], %2;\n\tselp.b32 %0,1,0,p;\n\t}" \
        : "=r"(_d) : "r"(_m), "r"(_p) : "memory"); \
    if (!_d) { asm volatile("{\n\t.reg .pred P1;\n\tWL%=:\n\tmbarrier.try_wait.parity.acquire.cta.shared::cta.b64 P1, [%0], %1, 0x989680;\n\t@P1 bra.uni WD%=;\n\tbra.uni WL%=;\n\tWD%=:\n\t}" \
        :: "r"(_m), "r"(_p) : "memory"); } } while(0)
#define MMA(c, a, b) asm volatile( \
    "mma.sync.aligned.m16n8k16.row.col.f32.f16.f16.f32 " \
    "{%0,%1,%2,%3},{%4,%5,%6,%7},{%8,%9},{%0,%1,%2,%3};" \
    : "+f"((c)[0]),"+f"((c)[1]),"+f"((c)[2]),"+f"((c)[3]) \
    : "r"((a)[0]),"r"((a)[1]),"r"((a)[2]),"r"((a)[3]),"r"((b)[0]),"r"((b)[1]))
#define LDSM4(r, a) asm volatile( \
    "ldmatrix.sync.aligned.m8n8.x4.shared.b16 {%0,%1,%2,%3}, [%4];" \
    : "=r"((r)[0]),"=r"((r)[1]),"=r"((r)[2]),"=r"((r)[3]) : "r"(a))

// ---------------- init ----------------
__global__ void k_init() {
    int i = blockIdx.x*blockDim.x + threadIdx.x;
    if (i < MAXROWS) g_slot_token[i] = 0;
    if (i < E) { g_counts[i] = 0; g_usage[i] = 0.f; }
}

// ---------------- gating ----------------
__global__ __launch_bounds__(256) void k_gate(const float* __restrict__ x,
                                              const float* __restrict__ Wg) {
    __shared__ float sWg[E*D];
    for (int i = threadIdx.x; i < E*D; i += blockDim.x) sWg[i] = Wg[i];
    __syncthreads();
    int warp = threadIdx.x >> 5, lane = threadIdx.x & 31;
    int t = blockIdx.x * 8 + warp;
    if (t >= TOK) return;
    const float* xr = x + (size_t)t * D;
    float acc[E];
    #pragma unroll
    for (int e = 0; e < E; e++) acc[e] = 0.f;
    for (int d = lane; d < D; d += 32) {
        float xv = xr[d];
        #pragma unroll
        for (int e = 0; e < E; e++) acc[e] += xv * sWg[e*D + d];
    }
    #pragma unroll
    for (int e = 0; e < E; e++)
        #pragma unroll
        for (int o = 16; o > 0; o >>= 1)
            acc[e] += __shfl_xor_sync(0xffffffffu, acc[e], o);
    if (lane == 0) {
        int i0 = 0; float v0 = acc[0];
        #pragma unroll
        for (int e = 1; e < E; e++) if (acc[e] > v0) { v0 = acc[e]; i0 = e; }
        int i1 = -1; float v1 = -INFINITY;
        #pragma unroll
        for (int e = 0; e < E; e++) if (e != i0 && acc[e] > v1) { v1 = acc[e]; i1 = e; }
        float ex = expf(v1 - v0);
        float inv = 1.f / (1.f + ex);
        g_eid[t*2] = i0; g_eid[t*2+1] = i1;
        g_gw[t*2]  = inv; g_gw[t*2+1] = ex * inv;
        atomicAdd(&g_counts[i0], 1); atomicAdd(&g_counts[i1], 1);
        atomicAdd(&g_usage[i0], inv); atomicAdd(&g_usage[i1], ex*inv);
    }
}

// ---------------- offsets + lb loss ----------------
__global__ void k_offsets(float* loss_out, int write_loss) {
    int off = 0;
    g_off[0] = 0;
    for (int e = 0; e < E; e++) {
        g_cursor[e] = off;
        off += (g_counts[e] + BM - 1) / BM * BM;
        g_off[e+1] = off;
    }
    g_total = off;
    if (write_loss) {
        float u[E]; float mean = 0.f;
        for (int e = 0; e < E; e++) { u[e] = g_usage[e] / (float)TOK; mean += u[e]; }
        mean /= (float)E;
        float var = 0.f;
        for (int e = 0; e < E; e++) { float d = u[e] - mean; var += d * d; }
        var /= (float)(E - 1);
        loss_out[0] = var * 0.01f;
    }
}

// ---------------- scatter ----------------
__global__ void k_scatter() {
    int i = blockIdx.x*blockDim.x + threadIdx.x;
    if (i >= TOK*2) return;
    int e = g_eid[i];
    int pos = atomicAdd(&g_cursor[e], 1);
    g_slot_token[pos] = i >> 1;
    g_slot_of[i] = pos;
}

// ---------------- prep A ----------------
__global__ __launch_bounds__(256) void k_prep_a(const float* __restrict__ x) {
    int id = blockIdx.x*256 + threadIdx.x;
    int gg = id & 7;
    int r  = (id >> 3) & 127;
    int c  = (id >> 10) & 15;
    int t  = id >> 14;
    if (t >= NROWT) return;
    int token = g_slot_token[t*128 + r];
    const float* src = x + (size_t)token*D + c*64 + gg*8;
    float4 v0 = *(const float4*)src;
    float4 v1 = *(const float4*)(src + 4);
    __half2 h0 = __floats2half2_rn(v0.x, v0.y);
    __half2 h1 = __floats2half2_rn(v0.z, v0.w);
    __half2 h2 = __floats2half2_rn(v1.x, v1.y);
    __half2 h3 = __floats2half2_rn(v1.z, v1.w);
    uint4 out = make_uint4(*(uint32_t*)&h0, *(uint32_t*)&h1, *(uint32_t*)&h2, *(uint32_t*)&h3);
    *(uint4*)(g_xa + ((size_t)(t*16 + c) << 14) + r*128 + ((gg ^ (r & 7)) << 4)) = out;
}

// ---------------- prep weights: coalesced uint4 stores ----------------
// 64 k-rows x 32 n-cols per block; thread packs 8 k into one 16B store.
__global__ void k_prep_w(const float* __restrict__ W, int R, int C, int which) {
    __shared__ float t[64][33];
    int e = blockIdx.z;
    int c0 = blockIdx.x * 32, r0 = blockIdx.y * 64;
    int tx = threadIdx.x, ty = threadIdx.y;
    const float* in = W + (size_t)e * R * C;
    #pragma unroll
    for (int i = ty; i < 64; i += 8)
        t[i][tx] = in[(size_t)(r0 + i) * C + c0 + tx];
    __syncthreads();
    uint8_t* outb = which ? g_w2t : g_w1t;
    int NBn = C >> 8, KCn = R >> 6;
    int kc = r0 >> 6;
    int n_local = ty*4 + (tx >> 3), ps = tx & 7;
    int n = c0 + n_local;
    int nb = n >> 8, nn = n & 255;
    int gg = ps ^ (nn & 7);
    uint32_t pk[4];
    #pragma unroll
    for (int jj = 0; jj < 4; jj++) {
        __half2 hv = __floats2half2_rn(t[gg*8 + 2*jj][n_local], t[gg*8 + 2*jj + 1][n_local]);
        pk[jj] = *(uint32_t*)&hv;
    }
    *(uint4*)(outb + ((size_t)((e*NBn + nb)*KCn + kc) << 15)
              + (nn << 7) + (ps << 4)) = *(uint4*)pk;
}

// ================= persistent fp16 GEMMs: 148 CTAs, continuous bulk ring =================
// smem: [full0 @ sb][full1 @ sb+8][data @ sb+1024]

__global__ void __launch_bounds__(NT, 1) k_gemm1_mma(const float* __restrict__ b1) {
    extern __shared__ __align__(128) char smem[];
    const int tid = threadIdx.x, wid = tid >> 5, lane = tid & 31;
    const int g = lane >> 2, t4 = lane & 3;
    const uint32_t sb = smem_u32(smem);

    const int NC = 8;                          // chunks per tile
    const int tiles = (g_total >> 7) * 16;     // row-tiles x 16 nb
    if ((int)blockIdx.x >= tiles) return;
    const int myTiles = (tiles - blockIdx.x + NSM - 1) / NSM;
    const int totC = myTiles * NC;

    if (tid == 0) { MBAR_INIT(sb + 0, 1); MBAR_INIT(sb + 8, 1); }
    __syncthreads();

    // refill helper state (tracked by all threads; only tid0 issues)
    int rf = 0;
    #define REFILL1() do { \
        int lt = rf / NC, cc = rf - lt*NC; \
        int tt = blockIdx.x + lt*NSM; \
        int tty = tt >> 4, nnb = tt & 15; \
        int row0r = tty << 7; \
        int er = 0; \
        _Pragma("unroll") \
        for (int i = 1; i < E; i++) if (row0r >= g_off[i]) er = i; \
        const uint8_t* Ab = g_xa + ((size_t)tty << 18); \
        const uint8_t* Bb = g_w1t + ((size_t)(er*16 + nnb) << 19); \
        int bb = rf & 1; \
        MBAR_EXPECT(sb + bb*8, STGB); \
        BULK(sb + 1024 + bb*STGB,      Ab + (size_t)cc*A2, A2, sb + bb*8); \
        BULK(sb + 1024 + bb*STGB + A2, Bb + (size_t)cc*B2, B2, sb + bb*8); \
    } while (0)

    if (tid == 0) { REFILL1(); rf = 1; REFILL1(); }
    rf = 2;

    const int lq = lane & 7;
    const int hiA = (lane >> 4) & 1, hiB = (lane >> 3) & 1;
    const int wm = (wid & 1) * 64, wn = (wid >> 1) * 32;
    uint32_t aRow[4], bRow[2];
    #pragma unroll
    for (int mt = 0; mt < 4; mt++)
        aRow[mt] = (uint32_t)((wm + mt*16 + lq + ((lane>>3)&1)*8) * 128);
    #pragma unroll
    for (int q = 0; q < 2; q++)
        bRow[q] = (uint32_t)(A2 + (wn + q*16 + ((lane>>4)&1)*8 + lq) * 128);

    int k = 0;
    for (int lt = 0; lt < myTiles; lt++) {
        const int t = blockIdx.x + lt*NSM;
        const int ty = t >> 4, nb = t & 15;
        const int row0 = ty << 7;
        int e = 0;
        #pragma unroll
        for (int i = 1; i < E; i++) if (row0 >= g_off[i]) e = i;
        const int n0 = nb << 8;

        float acc[4][4][4] = {};
        for (int c = 0; c < NC; c++) {
            int b = k & 1;
            MBAR_WAIT(sb + b*8, (k >> 1) & 1);
            const uint32_t sbase = sb + 1024 + b*STGB;
            #pragma unroll
            for (int hf = 0; hf < 2; hf++) {
                const uint32_t aSub = sbase + hf*16384;
                const uint32_t bSub = sbase + hf*32768;
                #pragma unroll
                for (int ks = 0; ks < 4; ks++) {
                    const uint32_t colA = (uint32_t)((((ks<<1)|hiA) ^ lq) << 4);
                    const uint32_t colB = (uint32_t)((((ks<<1)|hiB) ^ lq) << 4);
                    uint32_t a[4][4], bq[2][4];
                    #pragma unroll
                    for (int mt = 0; mt < 4; mt++) LDSM4(a[mt], aSub + aRow[mt] + colA);
                    #pragma unroll
                    for (int q = 0; q < 2; q++)    LDSM4(bq[q], bSub + bRow[q] + colB);
                    #pragma unroll
                    for (int mt = 0; mt < 4; mt++)
                        #pragma unroll
                        for (int nt = 0; nt < 4; nt++)
                            MMA(acc[mt][nt], a[mt], &bq[nt>>1][(nt&1)*2]);
                }
            }
            __syncthreads();
            if (tid == 0 && rf < totC) REFILL1();
            rf++;
            k++;
        }

        // epilogue: bias + exact gelu -> g_ht
        uint8_t* hb = g_ht + ((size_t)ty << 20);
        #pragma unroll
        for (int mt = 0; mt < 4; mt++) {
            #pragma unroll
            for (int nt = 0; nt < 4; nt++) {
                int col = n0 + wn + nt*8 + t4*2;
                float bi0 = __ldg(&b1[e*DFF + col]);
                float bi1 = __ldg(&b1[e*DFF + col + 1]);
                int kc = col >> 6, kk = col & 63;
                int gg = kk >> 3, b7 = kk & 7;
                #pragma unroll
                for (int h = 0; h < 2; h++) {
                    int r = wm + mt*16 + g + h*8;
                    float v0 = acc[mt][nt][2*h]   + bi0;
                    float v1 = acc[mt][nt][2*h+1] + bi1;
                    float g0 = 0.5f * v0 * (1.f + erff(v0 * 0.7071067811865476f));
                    float g1 = 0.5f * v1 * (1.f + erff(v1 * 0.7071067811865476f));
                    __half2 hv = __floats2half2_rn(g0, g1);
                    *(uint32_t*)(hb + ((size_t)kc << 14) + (r << 7)
                                 + ((gg ^ (r & 7)) << 4) + b7*2) = *(uint32_t*)&hv;
                }
            }
        }
    }
    #undef REFILL1
}

__global__ void __launch_bounds__(NT, 1) k_gemm2_mma(const float* __restrict__ b2) {
    extern __shared__ __align__(128) char smem[];
    const int tid = threadIdx.x, wid = tid >> 5, lane = tid & 31;
    const int g = lane >> 2, t4 = lane & 3;
    const uint32_t sb = smem_u32(smem);

    const int NC = 32;
    const int tiles = (g_total >> 7) * 4;
    if ((int)blockIdx.x >= tiles) return;
    const int myTiles = (tiles - blockIdx.x + NSM - 1) / NSM;
    const int totC = myTiles * NC;

    if (tid == 0) { MBAR_INIT(sb + 0, 1); MBAR_INIT(sb + 8, 1); }
    __syncthreads();

    int rf = 0;
    #define REFILL2() do { \
        int lt = rf / NC, cc = rf - lt*NC; \
        int tt = blockIdx.x + lt*NSM; \
        int tty = tt >> 2, nnb = tt & 3; \
        int row0r = tty << 7; \
        int er = 0; \
        _Pragma("unroll") \
        for (int i = 1; i < E; i++) if (row0r >= g_off[i]) er = i; \
        const uint8_t* Ab = g_ht + ((size_t)tty << 20); \
        const uint8_t* Bb = g_w2t + ((size_t)(er*4 + nnb) << 21); \
        int bb = rf & 1; \
        MBAR_EXPECT(sb + bb*8, STGB); \
        BULK(sb + 1024 + bb*STGB,      Ab + (size_t)cc*A2, A2, sb + bb*8); \
        BULK(sb + 1024 + bb*STGB + A2, Bb + (size_t)cc*B2, B2, sb + bb*8); \
    } while (0)

    if (tid == 0) { REFILL2(); rf = 1; REFILL2(); }
    rf = 2;

    const int lq = lane & 7;
    const int hiA = (lane >> 4) & 1, hiB = (lane >> 3) & 1;
    const int wm = (wid & 1) * 64, wn = (wid >> 1) * 32;
    uint32_t aRow[4], bRow[2];
    #pragma unroll
    for (int mt = 0; mt < 4; mt++)
        aRow[mt] = (uint32_t)((wm + mt*16 + lq + ((lane>>3)&1)*8) * 128);
    #pragma unroll
    for (int q = 0; q < 2; q++)
        bRow[q] = (uint32_t)(A2 + (wn + q*16 + ((lane>>4)&1)*8 + lq) * 128);

    int k = 0;
    for (int lt = 0; lt < myTiles; lt++) {
        const int t = blockIdx.x + lt*NSM;
        const int ty = t >> 2, nb = t & 3;
        const int row0 = ty << 7;
        int e = 0;
        #pragma unroll
        for (int i = 1; i < E; i++) if (row0 >= g_off[i]) e = i;
        const int n0 = nb << 8;

        float acc[4][4][4] = {};
        for (int c = 0; c < NC; c++) {
            int b = k & 1;
            MBAR_WAIT(sb + b*8, (k >> 1) & 1);
            const uint32_t sbase = sb + 1024 + b*STGB;
            #pragma unroll
            for (int hf = 0; hf < 2; hf++) {
                const uint32_t aSub = sbase + hf*16384;
                const uint32_t bSub = sbase + hf*32768;
                #pragma unroll
                for (int ks = 0; ks < 4; ks++) {
                    const uint32_t colA = (uint32_t)((((ks<<1)|hiA) ^ lq) << 4);
                    const uint32_t colB = (uint32_t)((((ks<<1)|hiB) ^ lq) << 4);
                    uint32_t a[4][4], bq[2][4];
                    #pragma unroll
                    for (int mt = 0; mt < 4; mt++) LDSM4(a[mt], aSub + aRow[mt] + colA);
                    #pragma unroll
                    for (int q = 0; q < 2; q++)    LDSM4(bq[q], bSub + bRow[q] + colB);
                    #pragma unroll
                    for (int mt = 0; mt < 4; mt++)
                        #pragma unroll
                        for (int nt = 0; nt < 4; nt++)
                            MMA(acc[mt][nt], a[mt], &bq[nt>>1][(nt&1)*2]);
                }
            }
            __syncthreads();
            if (tid == 0 && rf < totC) REFILL2();
            rf++;
            k++;
        }

        #pragma unroll
        for (int mt = 0; mt < 4; mt++) {
            #pragma unroll
            for (int nt = 0; nt < 4; nt++) {
                int col = n0 + wn + nt*8 + t4*2;
                float bi0 = __ldg(&b2[e*D + col]);
                float bi1 = __ldg(&b2[e*D + col + 1]);
                #pragma unroll
                for (int h = 0; h < 2; h++) {
                    int row = row0 + wm + mt*16 + g + h*8;
                    float2 v = make_float2(acc[mt][nt][2*h] + bi0, acc[mt][nt][2*h+1] + bi1);
                    *(float2*)(g_y + (size_t)row * D + col) = v;
                }
            }
        }
    }
    #undef REFILL2
}

// ---------------- combine ----------------
__global__ void k_combine(float* __restrict__ out) {
    int i = blockIdx.x*blockDim.x + threadIdx.x;
    if (i >= TOK*D) return;
    int t = i >> 10;
    int d = i & 1023;
    int s0 = g_slot_of[t*2], s1 = g_slot_of[t*2+1];
    out[i] = g_gw[t*2]   * g_y[(size_t)s0*D + d]
           + g_gw[t*2+1] * g_y[(size_t)s1*D + d];
}

// ---------------- launch ----------------
extern "C" void kernel_launch(void* const* d_in, const int* in_sizes, int n_in,
                              void* d_out, int out_size) {
    const float* x  = (const float*)d_in[0];
    const float* Wg = (const float*)d_in[1];
    const float* W1 = (const float*)d_in[2];
    const float* b1 = (const float*)d_in[3];
    const float* W2 = (const float*)d_in[4];
    const float* b2 = (const float*)d_in[5];
    float* out = (float*)d_out;

    cudaFuncSetAttribute(k_gemm1_mma, cudaFuncAttributeMaxDynamicSharedMemorySize, SMEM_BYTES);
    cudaFuncSetAttribute(k_gemm2_mma, cudaFuncAttributeMaxDynamicSharedMemorySize, SMEM_BYTES);

    k_init<<<(MAXROWS + 255)/256, 256>>>();
    k_gate<<<TOK/8, 256>>>(x, Wg);
    k_offsets<<<1,1>>>(out + (size_t)TOK*D, (out_size > TOK*D) ? 1 : 0);
    k_scatter<<<(TOK*2 + 255)/256, 256>>>();
    k_prep_a<<<(NROWT*16*128*8)/256, 256>>>(x);
    k_prep_w<<<dim3(DFF/32, D/64, E), dim3(32,8)>>>(W1, D, DFF, 0);
    k_prep_w<<<dim3(D/32, DFF/64, E), dim3(32,8)>>>(W2, DFF, D, 1);
    k_gemm1_mma<<<NSM, NT, SMEM_BYTES>>>(b1);
    k_gemm2_mma<<<NSM, NT, SMEM_BYTES>>>(b2);
    k_combine<<<(TOK*D + 255)/256, 256>>>(out);
}

// round 15
// speedup vs baseline: 1.0494x; 1.0494x over previous
#include <cuda_runtime.h>
#include <cuda_fp16.h>
#include <math.h>
#include <stdint.h>

#define D    1024
#define DFF  4096
#define E    8
#define TOK  8192
#define BM   128
#define BN   256
#define NT   512
#define NSM  148
#define STAGES 2
#define A2   32768           // A stage bytes (2 x 16KB kc chunks)
#define B2   65536           // B stage bytes (2 x 32KB kc chunks)
#define STGB (A2+B2)         // 98304
#define SMEM_BYTES (1024 + 2*STGB)   // 197632
#define MAXROWS (2*TOK + E*BM)     // 17408
#define NROWT (MAXROWS/BM)         // 136

// ---------------- scratch ----------------
__device__ int   g_eid[TOK*2];
__device__ float g_gw[TOK*2];
__device__ int   g_counts[E];
__device__ int   g_off[E+1];
__device__ int   g_cursor[E];
__device__ int   g_total;
__device__ int   g_slot_token[MAXROWS];
__device__ float g_slot_w[MAXROWS];
__device__ float g_usage[E];
__device__ uint8_t g_xa[(size_t)NROWT*16*16384];       // [tile][kc][16KB]
__device__ uint8_t g_w1t[(size_t)E*16*16*32768];       // [e][nb][kc][32KB]
__device__ uint8_t g_w2t[(size_t)E*4*64*32768];        // [e][nb][kc][32KB]
__device__ uint8_t g_ht[(size_t)NROWT*64*16384];       // [tile][kc][16KB]

// ---------------- helpers ----------------
__device__ __forceinline__ uint32_t smem_u32(const void* p) {
    uint32_t a;
    asm("{ .reg .u64 t; cvta.to.shared.u64 t, %1; cvt.u32.u64 %0, t; }" : "=r"(a) : "l"(p));
    return a;
}
#define MBAR_INIT(a,c) asm volatile("mbarrier.init.shared.b64 [%0], %1;" :: "r"(a), "r"(c) : "memory")
#define MBAR_EXPECT(a,tx) asm volatile("mbarrier.arrive.expect_tx.shared.b64 _, [%0], %1;" :: "r"(a), "r"(tx) : "memory")
#define BULK(dst, src, sz, bar) asm volatile( \
    "cp.async.bulk.shared::cluster.global.mbarrier::complete_tx::bytes [%0], [%1], %2, [%3];" \
    :: "r"(dst), "l"(src), "r"(sz), "r"(bar) : "memory")
#define MBAR_WAIT(a,p) do { uint32_t _m=(a); uint32_t _p=(p); uint32_t _d; \
    asm volatile("{\n\t.reg .pred p;\n\tmbarrier.try_wait.parity.acquire.cta.shared::cta.b64 p, [%1], %2;\n\tselp.b32 %0,1,0,p;\n\t}" \
        : "=r"(_d) : "r"(_m), "r"(_p) : "memory"); \
    if (!_d) { asm volatile("{\n\t.reg .pred P1;\n\tWL%=:\n\tmbarrier.try_wait.parity.acquire.cta.shared::cta.b64 P1, [%0], %1, 0x989680;\n\t@P1 bra.uni WD%=;\n\tbra.uni WL%=;\n\tWD%=:\n\t}" \
        :: "r"(_m), "r"(_p) : "memory"); } } while(0)
#define MMA(c, a, b) asm volatile( \
    "mma.sync.aligned.m16n8k16.row.col.f32.f16.f16.f32 " \
    "{%0,%1,%2,%3},{%4,%5,%6,%7},{%8,%9},{%0,%1,%2,%3};" \
    : "+f"((c)[0]),"+f"((c)[1]),"+f"((c)[2]),"+f"((c)[3]) \
    : "r"((a)[0]),"r"((a)[1]),"r"((a)[2]),"r"((a)[3]),"r"((b)[0]),"r"((b)[1]))
#define LDSM4(r, a) asm volatile( \
    "ldmatrix.sync.aligned.m8n8.x4.shared.b16 {%0,%1,%2,%3}, [%4];" \
    : "=r"((r)[0]),"=r"((r)[1]),"=r"((r)[2]),"=r"((r)[3]) : "r"(a))

// ---------------- init ----------------
__global__ void k_init() {
    int i = blockIdx.x*blockDim.x + threadIdx.x;
    if (i < MAXROWS) { g_slot_token[i] = 0; g_slot_w[i] = 0.f; }
    if (i < E) { g_counts[i] = 0; g_usage[i] = 0.f; }
}

// ---------------- gating ----------------
__global__ __launch_bounds__(256) void k_gate(const float* __restrict__ x,
                                              const float* __restrict__ Wg) {
    __shared__ float sWg[E*D];
    for (int i = threadIdx.x; i < E*D; i += blockDim.x) sWg[i] = Wg[i];
    __syncthreads();
    int warp = threadIdx.x >> 5, lane = threadIdx.x & 31;
    int t = blockIdx.x * 8 + warp;
    if (t >= TOK) return;
    const float* xr = x + (size_t)t * D;
    float acc[E];
    #pragma unroll
    for (int e = 0; e < E; e++) acc[e] = 0.f;
    for (int d = lane; d < D; d += 32) {
        float xv = xr[d];
        #pragma unroll
        for (int e = 0; e < E; e++) acc[e] += xv * sWg[e*D + d];
    }
    #pragma unroll
    for (int e = 0; e < E; e++)
        #pragma unroll
        for (int o = 16; o > 0; o >>= 1)
            acc[e] += __shfl_xor_sync(0xffffffffu, acc[e], o);
    if (lane == 0) {
        int i0 = 0; float v0 = acc[0];
        #pragma unroll
        for (int e = 1; e < E; e++) if (acc[e] > v0) { v0 = acc[e]; i0 = e; }
        int i1 = -1; float v1 = -INFINITY;
        #pragma unroll
        for (int e = 0; e < E; e++) if (e != i0 && acc[e] > v1) { v1 = acc[e]; i1 = e; }
        float ex = expf(v1 - v0);
        float inv = 1.f / (1.f + ex);
        g_eid[t*2] = i0; g_eid[t*2+1] = i1;
        g_gw[t*2]  = inv; g_gw[t*2+1] = ex * inv;
        atomicAdd(&g_counts[i0], 1); atomicAdd(&g_counts[i1], 1);
        atomicAdd(&g_usage[i0], inv); atomicAdd(&g_usage[i1], ex*inv);
    }
}

// ---------------- offsets + lb loss ----------------
__global__ void k_offsets(float* loss_out, int write_loss) {
    int off = 0;
    g_off[0] = 0;
    for (int e = 0; e < E; e++) {
        g_cursor[e] = off;
        off += (g_counts[e] + BM - 1) / BM * BM;
        g_off[e+1] = off;
    }
    g_total = off;
    if (write_loss) {
        float u[E]; float mean = 0.f;
        for (int e = 0; e < E; e++) { u[e] = g_usage[e] / (float)TOK; mean += u[e]; }
        mean /= (float)E;
        float var = 0.f;
        for (int e = 0; e < E; e++) { float d = u[e] - mean; var += d * d; }
        var /= (float)(E - 1);
        loss_out[0] = var * 0.01f;
    }
}

// ---------------- scatter ----------------
__global__ void k_scatter() {
    int i = blockIdx.x*blockDim.x + threadIdx.x;
    if (i >= TOK*2) return;
    int e = g_eid[i];
    int pos = atomicAdd(&g_cursor[e], 1);
    g_slot_token[pos] = i >> 1;
    g_slot_w[pos] = g_gw[i];
}

// ---------------- prep A ----------------
__global__ __launch_bounds__(256) void k_prep_a(const float* __restrict__ x) {
    int id = blockIdx.x*256 + threadIdx.x;
    int gg = id & 7;
    int r  = (id >> 3) & 127;
    int c  = (id >> 10) & 15;
    int t  = id >> 14;
    if (t >= NROWT) return;
    int token = g_slot_token[t*128 + r];
    const float* src = x + (size_t)token*D + c*64 + gg*8;
    float4 v0 = *(const float4*)src;
    float4 v1 = *(const float4*)(src + 4);
    __half2 h0 = __floats2half2_rn(v0.x, v0.y);
    __half2 h1 = __floats2half2_rn(v0.z, v0.w);
    __half2 h2 = __floats2half2_rn(v1.x, v1.y);
    __half2 h3 = __floats2half2_rn(v1.z, v1.w);
    uint4 out = make_uint4(*(uint32_t*)&h0, *(uint32_t*)&h1, *(uint32_t*)&h2, *(uint32_t*)&h3);
    *(uint4*)(g_xa + ((size_t)(t*16 + c) << 14) + r*128 + ((gg ^ (r & 7)) << 4)) = out;
}

// ---------------- prep weights: coalesced uint4 stores ----------------
__global__ void k_prep_w(const float* __restrict__ W, int R, int C, int which) {
    __shared__ float t[64][33];
    int e = blockIdx.z;
    int c0 = blockIdx.x * 32, r0 = blockIdx.y * 64;
    int tx = threadIdx.x, ty = threadIdx.y;
    const float* in = W + (size_t)e * R * C;
    #pragma unroll
    for (int i = ty; i < 64; i += 8)
        t[i][tx] = in[(size_t)(r0 + i) * C + c0 + tx];
    __syncthreads();
    uint8_t* outb = which ? g_w2t : g_w1t;
    int NBn = C >> 8, KCn = R >> 6;
    int kc = r0 >> 6;
    int n_local = ty*4 + (tx >> 3), ps = tx & 7;
    int n = c0 + n_local;
    int nb = n >> 8, nn = n & 255;
    int gg = ps ^ (nn & 7);
    uint32_t pk[4];
    #pragma unroll
    for (int jj = 0; jj < 4; jj++) {
        __half2 hv = __floats2half2_rn(t[gg*8 + 2*jj][n_local], t[gg*8 + 2*jj + 1][n_local]);
        pk[jj] = *(uint32_t*)&hv;
    }
    *(uint4*)(outb + ((size_t)((e*NBn + nb)*KCn + kc) << 15)
              + (nn << 7) + (ps << 4)) = *(uint4*)pk;
}

// ================= GEMM1 (R12 structure): per-tile CTAs, 2-stage bulk ring =================

__global__ void __launch_bounds__(NT, 1) k_gemm1_mma(const float* __restrict__ b1) {
    extern __shared__ __align__(128) char smem[];
    const int tid = threadIdx.x, wid = tid >> 5, lane = tid & 31;
    const int g = lane >> 2, t4 = lane & 3;
    const int row0 = blockIdx.y * BM;
    if (row0 >= g_total) return;
    int e = 0;
    #pragma unroll
    for (int i = 1; i < E; i++) if (row0 >= g_off[i]) e = i;
    const int n0 = blockIdx.x * BN;
    const int wm = (wid & 1) * 64, wn = (wid >> 1) * 32;
    const uint32_t sb = smem_u32(smem);

    const uint8_t* Abase = g_xa + ((size_t)blockIdx.y << 18);
    const uint8_t* Bbase = g_w1t + ((size_t)(e*16 + blockIdx.x) << 19);

    if (tid == 0) {
        MBAR_INIT(sb + 0, 1); MBAR_INIT(sb + 8, 1);
    }
    __syncthreads();
    if (tid == 0) {
        #pragma unroll
        for (int s = 0; s < STAGES; s++) {
            MBAR_EXPECT(sb + s*8, STGB);
            BULK(sb + 1024 + s*STGB,      Abase + (size_t)s*A2, A2, sb + s*8);
            BULK(sb + 1024 + s*STGB + A2, Bbase + (size_t)s*B2, B2, sb + s*8);
        }
    }

    const int lq = lane & 7;
    const int hiA = (lane >> 4) & 1, hiB = (lane >> 3) & 1;
    uint32_t aRow[4], bRow[2];
    #pragma unroll
    for (int mt = 0; mt < 4; mt++)
        aRow[mt] = (uint32_t)((wm + mt*16 + lq + ((lane>>3)&1)*8) * 128);
    #pragma unroll
    for (int q = 0; q < 2; q++)
        bRow[q] = (uint32_t)(A2 + (wn + q*16 + ((lane>>4)&1)*8 + lq) * 128);

    const int NC = 8;   // D / 128
    float acc[4][4][4] = {};
    uint32_t ph = 0;
    for (int c = 0; c < NC; c++) {
        int b = c & 1;
        MBAR_WAIT(sb + b*8, (ph >> b) & 1);
        ph ^= 1u << b;
        const uint32_t sbase = sb + 1024 + b*STGB;
        #pragma unroll
        for (int hf = 0; hf < 2; hf++) {
            const uint32_t aSub = sbase + hf*16384;
            const uint32_t bSub = sbase + hf*32768;
            #pragma unroll
            for (int ks = 0; ks < 4; ks++) {
                const uint32_t colA = (uint32_t)((((ks<<1)|hiA) ^ lq) << 4);
                const uint32_t colB = (uint32_t)((((ks<<1)|hiB) ^ lq) << 4);
                uint32_t a[4][4], bq[2][4];
                #pragma unroll
                for (int mt = 0; mt < 4; mt++) LDSM4(a[mt], aSub + aRow[mt] + colA);
                #pragma unroll
                for (int q = 0; q < 2; q++)    LDSM4(bq[q], bSub + bRow[q] + colB);
                #pragma unroll
                for (int mt = 0; mt < 4; mt++)
                    #pragma unroll
                    for (int nt = 0; nt < 4; nt++)
                        MMA(acc[mt][nt], a[mt], &bq[nt>>1][(nt&1)*2]);
            }
        }
        __syncthreads();
        if (c + STAGES < NC && tid == 0) {
            MBAR_EXPECT(sb + b*8, STGB);
            BULK(sbase,      Abase + (size_t)(c+STAGES)*A2, A2, sb + b*8);
            BULK(sbase + A2, Bbase + (size_t)(c+STAGES)*B2, B2, sb + b*8);
        }
    }

    // epilogue: bias + exact gelu -> g_ht (tile-chunk swizzled fp16)
    uint8_t* hb = g_ht + ((size_t)blockIdx.y << 20);
    #pragma unroll
    for (int mt = 0; mt < 4; mt++) {
        #pragma unroll
        for (int nt = 0; nt < 4; nt++) {
            int col = n0 + wn + nt*8 + t4*2;
            float bi0 = __ldg(&b1[e*DFF + col]);
            float bi1 = __ldg(&b1[e*DFF + col + 1]);
            int kc = col >> 6, kk = col & 63;
            int gg = kk >> 3, b7 = kk & 7;
            #pragma unroll
            for (int h = 0; h < 2; h++) {
                int r = wm + mt*16 + g + h*8;
                float v0 = acc[mt][nt][2*h]   + bi0;
                float v1 = acc[mt][nt][2*h+1] + bi1;
                float g0 = 0.5f * v0 * (1.f + erff(v0 * 0.7071067811865476f));
                float g1 = 0.5f * v1 * (1.f + erff(v1 * 0.7071067811865476f));
                __half2 hv = __floats2half2_rn(g0, g1);
                *(uint32_t*)(hb + ((size_t)kc << 14) + (r << 7)
                             + ((gg ^ (r & 7)) << 4) + b7*2) = *(uint32_t*)&hv;
            }
        }
    }
}

// ================= GEMM2: persistent (148 CTAs) + fused atomic combine =================

__global__ void __launch_bounds__(NT, 1) k_gemm2_mma(const float* __restrict__ b2,
                                                     float* __restrict__ out) {
    extern __shared__ __align__(128) char smem[];
    const int tid = threadIdx.x, wid = tid >> 5, lane = tid & 31;
    const int g = lane >> 2, t4 = lane & 3;
    const uint32_t sb = smem_u32(smem);

    const int NC = 32;
    const int tiles = (g_total >> 7) * 4;
    if ((int)blockIdx.x >= tiles) return;
    const int myTiles = (tiles - blockIdx.x + NSM - 1) / NSM;
    const int totC = myTiles * NC;

    if (tid == 0) { MBAR_INIT(sb + 0, 1); MBAR_INIT(sb + 8, 1); }
    __syncthreads();

    int rf = 0;
    #define REFILL2() do { \
        int lt = rf / NC, cc = rf - lt*NC; \
        int tt = blockIdx.x + lt*NSM; \
        int tty = tt >> 2, nnb = tt & 3; \
        int row0r = tty << 7; \
        int er = 0; \
        _Pragma("unroll") \
        for (int i = 1; i < E; i++) if (row0r >= g_off[i]) er = i; \
        const uint8_t* Ab = g_ht + ((size_t)tty << 20); \
        const uint8_t* Bb = g_w2t + ((size_t)(er*4 + nnb) << 21); \
        int bb = rf & 1; \
        MBAR_EXPECT(sb + bb*8, STGB); \
        BULK(sb + 1024 + bb*STGB,      Ab + (size_t)cc*A2, A2, sb + bb*8); \
        BULK(sb + 1024 + bb*STGB + A2, Bb + (size_t)cc*B2, B2, sb + bb*8); \
    } while (0)

    if (tid == 0) { REFILL2(); rf = 1; REFILL2(); }
    rf = 2;

    const int lq = lane & 7;
    const int hiA = (lane >> 4) & 1, hiB = (lane >> 3) & 1;
    const int wm = (wid & 1) * 64, wn = (wid >> 1) * 32;
    uint32_t aRow[4], bRow[2];
    #pragma unroll
    for (int mt = 0; mt < 4; mt++)
        aRow[mt] = (uint32_t)((wm + mt*16 + lq + ((lane>>3)&1)*8) * 128);
    #pragma unroll
    for (int q = 0; q < 2; q++)
        bRow[q] = (uint32_t)(A2 + (wn + q*16 + ((lane>>4)&1)*8 + lq) * 128);

    int k = 0;
    for (int lt = 0; lt < myTiles; lt++) {
        const int t = blockIdx.x + lt*NSM;
        const int ty = t >> 2, nb = t & 3;
        const int row0 = ty << 7;
        int e = 0;
        #pragma unroll
        for (int i = 1; i < E; i++) if (row0 >= g_off[i]) e = i;
        const int n0 = nb << 8;

        float acc[4][4][4] = {};
        for (int c = 0; c < NC; c++) {
            int b = k & 1;
            MBAR_WAIT(sb + b*8, (k >> 1) & 1);
            const uint32_t sbase = sb + 1024 + b*STGB;
            #pragma unroll
            for (int hf = 0; hf < 2; hf++) {
                const uint32_t aSub = sbase + hf*16384;
                const uint32_t bSub = sbase + hf*32768;
                #pragma unroll
                for (int ks = 0; ks < 4; ks++) {
                    const uint32_t colA = (uint32_t)((((ks<<1)|hiA) ^ lq) << 4);
                    const uint32_t colB = (uint32_t)((((ks<<1)|hiB) ^ lq) << 4);
                    uint32_t a[4][4], bq[2][4];
                    #pragma unroll
                    for (int mt = 0; mt < 4; mt++) LDSM4(a[mt], aSub + aRow[mt] + colA);
                    #pragma unroll
                    for (int q = 0; q < 2; q++)    LDSM4(bq[q], bSub + bRow[q] + colB);
                    #pragma unroll
                    for (int mt = 0; mt < 4; mt++)
                        #pragma unroll
                        for (int nt = 0; nt < 4; nt++)
                            MMA(acc[mt][nt], a[mt], &bq[nt>>1][(nt&1)*2]);
                }
            }
            __syncthreads();
            if (tid == 0 && rf < totC) REFILL2();
            rf++;
            k++;
        }

        // fused combine: out[token, col] += w_slot * (acc + bias)
        #pragma unroll
        for (int mt = 0; mt < 4; mt++) {
            #pragma unroll
            for (int h = 0; h < 2; h++) {
                int row = row0 + wm + mt*16 + g + h*8;
                int tok = __ldg(&g_slot_token[row]);
                float w = __ldg(&g_slot_w[row]);
                float* orow = out + (size_t)tok * D;
                #pragma unroll
                for (int nt = 0; nt < 4; nt++) {
                    int col = n0 + wn + nt*8 + t4*2;
                    float bi0 = __ldg(&b2[e*D + col]);
                    float bi1 = __ldg(&b2[e*D + col + 1]);
                    atomicAdd(orow + col,     w * (acc[mt][nt][2*h]   + bi0));
                    atomicAdd(orow + col + 1, w * (acc[mt][nt][2*h+1] + bi1));
                }
            }
        }
    }
    #undef REFILL2
}

// ---------------- launch ----------------
extern "C" void kernel_launch(void* const* d_in, const int* in_sizes, int n_in,
                              void* d_out, int out_size) {
    const float* x  = (const float*)d_in[0];
    const float* Wg = (const float*)d_in[1];
    const float* W1 = (const float*)d_in[2];
    const float* b1 = (const float*)d_in[3];
    const float* W2 = (const float*)d_in[4];
    const float* b2 = (const float*)d_in[5];
    float* out = (float*)d_out;

    cudaFuncSetAttribute(k_gemm1_mma, cudaFuncAttributeMaxDynamicSharedMemorySize, SMEM_BYTES);
    cudaFuncSetAttribute(k_gemm2_mma, cudaFuncAttributeMaxDynamicSharedMemorySize, SMEM_BYTES);

    cudaMemsetAsync(out, 0, (size_t)TOK*D*sizeof(float));
    k_init<<<(MAXROWS + 255)/256, 256>>>();
    k_gate<<<TOK/8, 256>>>(x, Wg);
    k_offsets<<<1,1>>>(out + (size_t)TOK*D, (out_size > TOK*D) ? 1 : 0);
    k_scatter<<<(TOK*2 + 255)/256, 256>>>();
    k_prep_a<<<(NROWT*16*128*8)/256, 256>>>(x);
    k_prep_w<<<dim3(DFF/32, D/64, E), dim3(32,8)>>>(W1, D, DFF, 0);
    k_prep_w<<<dim3(D/32, DFF/64, E), dim3(32,8)>>>(W2, DFF, D, 1);
    k_gemm1_mma<<<dim3(DFF/BN, NROWT), NT, SMEM_BYTES>>>(b1);
    k_gemm2_mma<<<NSM, NT, SMEM_BYTES>>>(b2, out);
}